// round 13
// baseline (speedup 1.0000x reference)
#include <cuda_runtime.h>
#include <cuda_bf16.h>
#include <cstdint>

typedef unsigned long long ull;

#define CC   64
#define HH   128
#define WW   128
#define BB   8
#define HW   (HH*WW)        // 16384
#define CHW  (CC*HW)        // 1048576

// pre-split, pre-transposed planes: ushort [n][y][x][ci(64)]
__device__ unsigned short g_featFH[BB*HH*WW*64];
__device__ unsigned short g_featFL[BB*HH*WW*64];
__device__ unsigned short g_featRH[BB*HH*WW*64];
__device__ unsigned short g_featRL[BB*HH*WW*64];
__device__ unsigned short g_xH[BB*HH*WW*64];
__device__ unsigned short g_xL[BB*HH*WW*64];
// pre-split conv weights: [slot54][o192][ci32] ushort; slot = (kh*3+kw)*6+cg
__device__ unsigned short g_Wh[54*192*32];
__device__ unsigned short g_Wl[54*192*32];

// ---------------- f32x2 helpers ----------------
__device__ __forceinline__ ull pk2(float lo, float hi){
    ull r; asm("mov.b64 %0, {%1,%2};" : "=l"(r) : "f"(lo), "f"(hi)); return r;
}
__device__ __forceinline__ void unpk(ull a, float& lo, float& hi){
    asm("mov.b64 {%0,%1}, %2;" : "=f"(lo), "=f"(hi) : "l"(a));
}
__device__ __forceinline__ void fma2(ull& d, ull a, ull b){
    asm("fma.rn.f32x2 %0, %1, %2, %0;" : "+l"(d) : "l"(a), "l"(b));
}
__device__ __forceinline__ ull add2(ull a, ull b){
    ull r; asm("add.rn.f32x2 %0, %1, %2;" : "=l"(r) : "l"(a), "l"(b)); return r;
}

// ---------------- misc helpers ----------------
__device__ __forceinline__ uint32_t smem_u32(const void* p){
    uint32_t a;
    asm("{ .reg .u64 t; cvta.to.shared.u64 t, %1; cvt.u32.u64 %0, t; }" : "=r"(a) : "l"(p));
    return a;
}
__device__ __forceinline__ void cp_async16(uint32_t dst, const void* src, int szbytes){
    asm volatile("cp.async.cg.shared.global [%0], [%1], 16, %2;"
                 :: "r"(dst), "l"(src), "r"(szbytes) : "memory");
}
__device__ __forceinline__ void cp_commit(){ asm volatile("cp.async.commit_group;" ::: "memory"); }
__device__ __forceinline__ void cp_wait0(){ asm volatile("cp.async.wait_group 0;" ::: "memory"); }

__device__ __forceinline__ void bsplit(float v, unsigned short& h, unsigned short& l){
    __nv_bfloat16 hb = __float2bfloat16(v);
    float r = v - __bfloat162float(hb);
    __nv_bfloat16 lb = __float2bfloat16(r);
    h = __bfloat16_as_ushort(hb); l = __bfloat16_as_ushort(lb);
}

__device__ __forceinline__ void mma16816(float* d, const uint32_t* a, uint32_t b0, uint32_t b1){
    asm volatile(
        "mma.sync.aligned.m16n8k16.row.col.f32.bf16.bf16.f32 "
        "{%0,%1,%2,%3}, {%4,%5,%6,%7}, {%8,%9}, {%0,%1,%2,%3};"
        : "+f"(d[0]), "+f"(d[1]), "+f"(d[2]), "+f"(d[3])
        : "r"(a[0]), "r"(a[1]), "r"(a[2]), "r"(a[3]), "r"(b0), "r"(b1));
}
__device__ __forceinline__ void ldsm_x4(uint32_t* r, uint32_t addr){
    asm volatile("ldmatrix.sync.aligned.m8n8.x4.shared.b16 {%0,%1,%2,%3}, [%4];"
        : "=r"(r[0]), "=r"(r[1]), "=r"(r[2]), "=r"(r[3]) : "r"(addr));
}

// ---------------- weight prep ----------------
__global__ void wprep_kernel(const float* __restrict__ Wmsa)
{
    int slot = blockIdx.x;              // (kh*3+kw)*6 + cg
    int tap = slot / 6, cg = slot % 6;
    const int i0 = blockIdx.y * 1536;
    for (int idx = i0 + threadIdx.x; idx < i0 + 1536; idx += 256) {
        int o = idx >> 5, cil = idx & 31;
        int ci = cg*32 + cil;
        float w = Wmsa[(size_t)o*1728 + ci*9 + tap];
        unsigned short h, l; bsplit(w, h, l);
        g_Wh[(size_t)slot*6144 + idx] = h;
        g_Wl[(size_t)slot*6144 + idx] = l;
    }
}

// ---------------- x prep: NCHW float -> [n][y][x][c] split planes ----------------
__global__ void xprep_kernel(const float* __restrict__ x)
{
    __shared__ float row[64*130];
    const int y = blockIdx.x, n = blockIdx.y;
    const int tid = threadIdx.x;
    const float* src = x + (size_t)n*CHW + y*WW;
    for (int idx = tid; idx < 64*128; idx += 256) {
        int c = idx >> 7, xx = idx & 127;
        row[c*130 + xx] = src[(size_t)c*HW + xx];
    }
    __syncthreads();
    for (int idx = tid; idx < 128*16; idx += 256) {
        int xx = idx >> 4, c0 = (idx & 15)*4;
        ushort4 h4, l4;
        unsigned short h, l;
        bsplit(row[(c0+0)*130 + xx], h, l); h4.x = h; l4.x = l;
        bsplit(row[(c0+1)*130 + xx], h, l); h4.y = h; l4.y = l;
        bsplit(row[(c0+2)*130 + xx], h, l); h4.z = h; l4.z = l;
        bsplit(row[(c0+3)*130 + xx], h, l); h4.w = h; l4.w = l;
        size_t base = (((size_t)n*HH + y)*WW + xx)*64 + c0;
        *reinterpret_cast<ushort4*>(&g_xH[base]) = h4;
        *reinterpret_cast<ushort4*>(&g_xL[base]) = l4;
    }
}

// ---------------- attn kernel (512 threads) ----------------
#define BSTRIDE 130
#define WSTRIDE 65
#define SMEM1_BYTES (64*WSTRIDE*8 + 3*64*BSTRIDE*4 + 64*4)
#define ATHREADS 512

__device__ __forceinline__ void load_row130(float* dst, const float* src, int tid){
    for (int idx = tid; idx < 64*128; idx += ATHREADS) {
        int c = idx >> 7, xx = idx & 127;
        dst[c*BSTRIDE + xx] = src[c*HW + xx];
    }
}
__device__ __forceinline__ void load_wdup(ull* WS, float* bst,
                                          const float* Wg, const float* bg, int tid){
    for (int idx = tid; idx < 4096; idx += ATHREADS) {
        int o = idx >> 6, k = idx & 63;
        float w = Wg[idx];
        WS[k*WSTRIDE + o] = pk2(w, w);
    }
    if (tid < 64) bst[tid] = bg[tid];
}
// out[o][pixpair]: o=o0+i (4), pixel pair at bytes 2*tx + 64*jj (jj<2)
__device__ __forceinline__ void mm64p(const ull* __restrict__ A2,
                                      const float* __restrict__ Bm,
                                      int o0, int tx, ull acc[4][2]){
    #pragma unroll
    for (int i = 0; i < 4; i++)
        #pragma unroll
        for (int j = 0; j < 2; j++) acc[i][j] = 0ull;
    #pragma unroll 4
    for (int k = 0; k < 64; k++) {
        ull a0 = A2[k*WSTRIDE + o0    ];
        ull a1 = A2[k*WSTRIDE + o0 + 1];
        ull a2 = A2[k*WSTRIDE + o0 + 2];
        ull a3 = A2[k*WSTRIDE + o0 + 3];
        const float* bp = Bm + k*BSTRIDE + 2*tx;
        #pragma unroll
        for (int jj = 0; jj < 2; jj++) {
            ull b = *reinterpret_cast<const ull*>(bp + 64*jj);
            fma2(acc[0][jj], a0, b);
            fma2(acc[1][jj], a1, b);
            fma2(acc[2][jj], a2, b);
            fma2(acc[3][jj], a3, b);
        }
    }
}
// score[c][d] = sum_w Am[c][w]*Bm[d][w]; c=o0+i, d=tx+32j; write WS[d*65+c]={s,s}
__device__ __forceinline__ void sc128p(const float* __restrict__ Am,
                                       const float* __restrict__ Bm,
                                       int o0, int tx, ull* WS){
    ull acc[4][2];
    #pragma unroll
    for (int i = 0; i < 4; i++)
        #pragma unroll
        for (int j = 0; j < 2; j++) acc[i][j] = 0ull;
    #pragma unroll 4
    for (int kp = 0; kp < 64; kp++) {
        ull a[4], b[2];
        #pragma unroll
        for (int i = 0; i < 4; i++)
            a[i] = *reinterpret_cast<const ull*>(Am + (o0+i)*BSTRIDE + 2*kp);
        #pragma unroll
        for (int j = 0; j < 2; j++)
            b[j] = *reinterpret_cast<const ull*>(Bm + (tx+32*j)*BSTRIDE + 2*kp);
        #pragma unroll
        for (int i = 0; i < 4; i++)
            #pragma unroll
            for (int j = 0; j < 2; j++) fma2(acc[i][j], a[i], b[j]);
    }
    #pragma unroll
    for (int i = 0; i < 4; i++)
        #pragma unroll
        for (int j = 0; j < 2; j++) {
            float lo, hi; unpk(acc[i][j], lo, hi);
            float s = lo + hi;
            WS[(tx+32*j)*WSTRIDE + o0 + i] = pk2(s, s);
        }
}
__device__ __forceinline__ void add_bias_store(float* Buf, ull acc[4][2],
                                               const float* bst, int o0, int tx){
    #pragma unroll
    for (int i = 0; i < 4; i++) {
        ull bb = pk2(bst[o0+i], bst[o0+i]);
        #pragma unroll
        for (int jj = 0; jj < 2; jj++)
            *reinterpret_cast<ull*>(Buf + (o0+i)*BSTRIDE + 2*tx + 64*jj) = add2(acc[i][jj], bb);
    }
}
// store acc (feature values) as split planes at [n][y][x][ci]
__device__ __forceinline__ void store_feat_planes(
    unsigned short* __restrict__ gH, unsigned short* __restrict__ gL,
    ull acc[4][2], int n, int y, int o0, int tx)
{
    #pragma unroll
    for (int jj = 0; jj < 2; jj++) {
        float lo[4], hi[4];
        #pragma unroll
        for (int i = 0; i < 4; i++) unpk(acc[i][jj], lo[i], hi[i]);
        #pragma unroll
        for (int e = 0; e < 2; e++) {
            int xx = 2*tx + 64*jj + e;
            ushort4 h4, l4;
            unsigned short h, l;
            bsplit(e ? hi[0] : lo[0], h, l); h4.x = h; l4.x = l;
            bsplit(e ? hi[1] : lo[1], h, l); h4.y = h; l4.y = l;
            bsplit(e ? hi[2] : lo[2], h, l); h4.z = h; l4.z = l;
            bsplit(e ? hi[3] : lo[3], h, l); h4.w = h; l4.w = l;
            size_t base = (((size_t)n*HH + y)*WW + xx)*64 + o0;
            *reinterpret_cast<ushort4*>(&gH[base]) = h4;
            *reinterpret_cast<ushort4*>(&gL[base]) = l4;
        }
    }
}

__global__ void __launch_bounds__(ATHREADS, 1)
attn_kernel(const float* __restrict__ x,  const float* __restrict__ xf, const float* __restrict__ xr,
            const float* __restrict__ Wx,  const float* __restrict__ bx,
            const float* __restrict__ Wx1, const float* __restrict__ bx1,
            const float* __restrict__ Wx2, const float* __restrict__ bx2,
            const float* __restrict__ Wxf, const float* __restrict__ bxf,
            const float* __restrict__ Wxr, const float* __restrict__ bxr)
{
    extern __shared__ ull smu[];
    ull*   WS   = smu;
    float* BufA = (float*)(WS + 64*WSTRIDE);
    float* BufP = BufA + 64*BSTRIDE;
    float* BufF = BufP + 64*BSTRIDE;
    float* bst  = BufF + 64*BSTRIDE;

    const int tid = threadIdx.x;
    const int ty = tid >> 5, tx = tid & 31;
    const int o0 = ty*4;
    const int y = blockIdx.x, n = blockIdx.y;
    const int rowoff = n*CHW + y*WW;

    ull acc[4][2];

    // 1) xp = Wx@x + bx -> BufP
    load_row130(BufA, x + rowoff, tid);
    load_wdup(WS, bst, Wx, bx, tid);
    __syncthreads();
    mm64p(WS, BufA, o0, tx, acc);
    add_bias_store(BufP, acc, bst, o0, tx);
    __syncthreads();

    // 2) xfp = Wxf@xf -> BufF (in place)
    load_row130(BufF, xf + rowoff, tid);
    load_wdup(WS, bst, Wxf, bxf, tid);
    __syncthreads();
    mm64p(WS, BufF, o0, tx, acc);
    __syncthreads();
    add_bias_store(BufF, acc, bst, o0, tx);
    __syncthreads();

    // 3) x1 = Wx1@xp -> BufA
    load_wdup(WS, bst, Wx1, bx1, tid);
    __syncthreads();
    mm64p(WS, BufP, o0, tx, acc);
    add_bias_store(BufA, acc, bst, o0, tx);
    __syncthreads();

    // 4) score1 -> WS
    sc128p(BufA, BufF, o0, tx, WS);
    __syncthreads();

    // 5) featF = score1 @ xp -> planes
    mm64p(WS, BufP, o0, tx, acc);
    store_feat_planes(g_featFH, g_featFL, acc, n, y, o0, tx);
    __syncthreads();

    // 6) xrp = Wxr@xr -> BufF
    load_row130(BufF, xr + rowoff, tid);
    load_wdup(WS, bst, Wxr, bxr, tid);
    __syncthreads();
    mm64p(WS, BufF, o0, tx, acc);
    __syncthreads();
    add_bias_store(BufF, acc, bst, o0, tx);
    __syncthreads();

    // 7) x2 = Wx2@xp -> BufA
    load_wdup(WS, bst, Wx2, bx2, tid);
    __syncthreads();
    mm64p(WS, BufP, o0, tx, acc);
    add_bias_store(BufA, acc, bst, o0, tx);
    __syncthreads();

    // 8) score2 -> WS
    sc128p(BufA, BufF, o0, tx, WS);
    __syncthreads();

    // 9) featR -> planes
    mm64p(WS, BufP, o0, tx, acc);
    store_feat_planes(g_featRH, g_featRL, acc, n, y, o0, tx);
}

// ---------------- conv kernel: mma.sync bf16, ldmatrix frags ----------------
// block=(y,n), 512 threads (16 warps: wm 0..3 -> M48, wn 0..3 -> N32).
// 18 stages (kh 0..2, cg 0..5). Per buffer:
//   A: 6 tiles [kw(3)][h/l(2)] of [192 o][32 k, 80B-stride]  = 92160 B
//   B: Bh,Bl [130 rows(x+1)][32 k, 80B-stride]               = 20800 B
#define ATILE   15360   // 192*80
#define ABUF    92160
#define BPLANE  10400   // 130*80
#define BUFB    112960  // ABUF + 2*BPLANE
#define CONV_SMEM (2*BUFB)   // 225920

__device__ __forceinline__ void conv_issueA(uint32_t dst_base, int s, int tid)
{
    const int kh = s/6, cg = s - (s/6)*6;
    #pragma unroll 3
    for (int q = tid; q < 4608; q += 512) {
        int t   = q / 768;             // kw*2 + hl
        int rem = q - t*768;
        int o   = rem >> 2, c16 = rem & 3;
        int kw  = t >> 1,   hl = t & 1;
        int slot = (kh*3 + kw)*6 + cg;
        const unsigned short* src = (hl ? g_Wl : g_Wh) + (size_t)slot*6144 + o*32 + c16*8;
        cp_async16(dst_base + t*ATILE + o*80 + c16*16, src, 16);
    }
}

__device__ __forceinline__ void conv_issueB(uint32_t dst_base, int s, int n, int y, int tid)
{
    const int kh = s/6, cg = s - (s/6)*6;
    const unsigned short *pH, *pL;
    if      (cg < 2) { pH = g_featFH; pL = g_featFL; }
    else if (cg < 4) { pH = g_featRH; pL = g_featRL; }
    else             { pH = g_xH;     pL = g_xL;     }
    const int coff = (cg & 1)*32;
    const int iy = y - 1 + kh;
    const bool vrow = (iy >= 0 && iy < HH);
    #pragma unroll 3
    for (int q = tid; q < 1040; q += 512) {
        int col = q >> 3, t = q & 7;
        int plane = t >> 2, c16 = t & 3;
        int gx = col - 1;
        bool ok = vrow && gx >= 0 && gx < WW;
        const unsigned short* p = plane ? pL : pH;
        const unsigned short* src = ok
            ? p + (((size_t)n*HH + iy)*WW + gx)*64 + coff + c16*8
            : p;
        cp_async16(dst_base + ABUF + plane*BPLANE + col*80 + c16*16, src, ok ? 16 : 0);
    }
}

__global__ void __launch_bounds__(512, 1)
conv_mma_kernel(const float* __restrict__ bmsa, const float* __restrict__ gamma,
                const float* __restrict__ beta, const float* __restrict__ mean,
                const float* __restrict__ var,  float* __restrict__ out)
{
    extern __shared__ char smem[];
    const uint32_t smem_base = smem_u32(smem);
    const int tid  = threadIdx.x;
    const int lane = tid & 31, wid = tid >> 5;
    const int wm = wid >> 2;           // 0..3 -> M offset 48*wm
    const int wn = wid & 3;            // 0..3 -> N offset 32*wn
    const int y = blockIdx.x, n = blockIdx.y;

    // ldmatrix lane address patterns
    const uint32_t aPat = (uint32_t)(wm*3840 + (lane & 15)*80 + (lane >> 4)*16);
    const uint32_t bPat = (uint32_t)(ABUF + (wn*32 + lane)*80);

    float acc[3][4][4];
    #pragma unroll
    for (int mi = 0; mi < 3; mi++)
        #pragma unroll
        for (int nb = 0; nb < 4; nb++)
            #pragma unroll
            for (int e = 0; e < 4; e++) acc[mi][nb][e] = 0.f;

    // prologue: stage 0 into buf0
    conv_issueA(smem_base, 0, tid);
    conv_issueB(smem_base, 0, n, y, tid);
    cp_commit();

    for (int s = 0; s < 18; s++) {
        const int b = s & 1;
        const uint32_t bufo = smem_base + b*BUFB;

        cp_wait0();
        __syncthreads();

        if (s < 17) {
            conv_issueA(smem_base + (b^1)*BUFB, s+1, tid);
            conv_issueB(smem_base + (b^1)*BUFB, s+1, n, y, tid);
            cp_commit();
        }

        #pragma unroll
        for (int kw = 0; kw < 3; kw++) {
            const uint32_t AhB = bufo + (kw*2 + 0)*ATILE + aPat;
            const uint32_t AlB = AhB + ATILE;
            const uint32_t Bba = bufo + bPat + kw*80;
            #pragma unroll
            for (int ks = 0; ks < 2; ks++) {
                const uint32_t ko = ks*32;
                uint32_t bH[8], bL[8], aF[3][4];
                ldsm_x4(bH,     Bba + ko);                // b0: nb0..3 (k0-7)
                ldsm_x4(bH + 4, Bba + ko + 16);           // b1: nb0..3 (k8-15)
                ldsm_x4(bL,     Bba + BPLANE + ko);
                ldsm_x4(bL + 4, Bba + BPLANE + ko + 16);
                #pragma unroll
                for (int mi = 0; mi < 3; mi++)
                    ldsm_x4(aF[mi], AhB + mi*1280 + ko);
                #pragma unroll
                for (int nb = 0; nb < 4; nb++)
                    #pragma unroll
                    for (int mi = 0; mi < 3; mi++) {
                        mma16816(acc[mi][nb], aF[mi], bH[nb], bH[4+nb]);
                        mma16816(acc[mi][nb], aF[mi], bL[nb], bL[4+nb]);
                    }
                #pragma unroll
                for (int mi = 0; mi < 3; mi++)
                    ldsm_x4(aF[mi], AlB + mi*1280 + ko);
                #pragma unroll
                for (int nb = 0; nb < 4; nb++)
                    #pragma unroll
                    for (int mi = 0; mi < 3; mi++)
                        mma16816(acc[mi][nb], aF[mi], bH[nb], bH[4+nb]);
            }
        }
    }

    // ---- epilogue: bias + BN + ReLU, float2 stores ----
    #pragma unroll
    for (int mi = 0; mi < 3; mi++) {
        #pragma unroll
        for (int h = 0; h < 2; h++) {
            const int o = wm*48 + mi*16 + (lane >> 2) + h*8;
            const float sc = gamma[o] * rsqrtf(var[o] + 1e-4f);
            const float t0 = (bmsa[o] - mean[o]) * sc + beta[o];
            float* orow = out + (((size_t)n*192 + o)*HH + y)*WW;
            #pragma unroll
            for (int nb = 0; nb < 4; nb++) {
                const int x0 = wn*32 + nb*8 + (lane & 3)*2;
                float v0 = fmaxf(fmaf(acc[mi][nb][h*2+0], sc, t0), 0.f);
                float v1 = fmaxf(fmaf(acc[mi][nb][h*2+1], sc, t0), 0.f);
                *reinterpret_cast<ull*>(orow + x0) = pk2(v0, v1);
            }
        }
    }
}

// ---------------- launch ----------------
extern "C" void kernel_launch(void* const* d_in, const int* in_sizes, int n_in,
                              void* d_out, int out_size)
{
    const float* x    = (const float*)d_in[0];
    const float* xf   = (const float*)d_in[1];
    const float* xr   = (const float*)d_in[2];
    const float* Wx   = (const float*)d_in[3];
    const float* bx   = (const float*)d_in[4];
    const float* Wx1  = (const float*)d_in[5];
    const float* bx1  = (const float*)d_in[6];
    const float* Wx2  = (const float*)d_in[7];
    const float* bx2  = (const float*)d_in[8];
    const float* Wxf  = (const float*)d_in[9];
    const float* bxf  = (const float*)d_in[10];
    const float* Wxr  = (const float*)d_in[11];
    const float* bxr  = (const float*)d_in[12];
    const float* Wmsa = (const float*)d_in[13];
    const float* bmsa = (const float*)d_in[14];
    const float* gam  = (const float*)d_in[15];
    const float* bet  = (const float*)d_in[16];
    const float* mu   = (const float*)d_in[17];
    const float* var  = (const float*)d_in[18];
    float* out = (float*)d_out;

    cudaFuncSetAttribute(attn_kernel, cudaFuncAttributeMaxDynamicSharedMemorySize, SMEM1_BYTES);
    cudaFuncSetAttribute(conv_mma_kernel, cudaFuncAttributeMaxDynamicSharedMemorySize, CONV_SMEM);

    dim3 gw(54, 4);
    wprep_kernel<<<gw, 256>>>(Wmsa);
    dim3 gx2(HH, BB);
    xprep_kernel<<<gx2, 256>>>(x);

    dim3 g1(HH, BB);
    attn_kernel<<<g1, ATHREADS, SMEM1_BYTES>>>(x, xf, xr, Wx, bx, Wx1, bx1, Wx2, bx2,
                                               Wxf, bxf, Wxr, bxr);

    dim3 g2(HH, BB);
    conv_mma_kernel<<<g2, 512, CONV_SMEM>>>(bmsa, gam, bet, mu, var, out);
}

// round 14
// speedup vs baseline: 1.3187x; 1.3187x over previous
#include <cuda_runtime.h>
#include <cuda_bf16.h>
#include <cstdint>

typedef unsigned long long ull;

#define CC   64
#define HH   128
#define WW   128
#define BB   8
#define HW   (HH*WW)        // 16384
#define CHW  (CC*HW)        // 1048576

// pre-split, pre-transposed planes: ushort [n][y][x][ci(64)]
__device__ unsigned short g_featFH[BB*HH*WW*64];
__device__ unsigned short g_featFL[BB*HH*WW*64];
__device__ unsigned short g_featRH[BB*HH*WW*64];
__device__ unsigned short g_featRL[BB*HH*WW*64];
__device__ unsigned short g_xH[BB*HH*WW*64];
__device__ unsigned short g_xL[BB*HH*WW*64];
// pre-split conv weights: [slot54][o192][ci32] ushort; slot = (kh*3+kw)*6+cg
__device__ unsigned short g_Wh[54*192*32];
__device__ unsigned short g_Wl[54*192*32];

// ---------------- f32x2 helpers ----------------
__device__ __forceinline__ ull pk2(float lo, float hi){
    ull r; asm("mov.b64 %0, {%1,%2};" : "=l"(r) : "f"(lo), "f"(hi)); return r;
}
__device__ __forceinline__ void unpk(ull a, float& lo, float& hi){
    asm("mov.b64 {%0,%1}, %2;" : "=f"(lo), "=f"(hi) : "l"(a));
}
__device__ __forceinline__ void fma2(ull& d, ull a, ull b){
    asm("fma.rn.f32x2 %0, %1, %2, %0;" : "+l"(d) : "l"(a), "l"(b));
}
__device__ __forceinline__ ull add2(ull a, ull b){
    ull r; asm("add.rn.f32x2 %0, %1, %2;" : "=l"(r) : "l"(a), "l"(b)); return r;
}

// ---------------- misc helpers ----------------
__device__ __forceinline__ uint32_t smem_u32(const void* p){
    uint32_t a;
    asm("{ .reg .u64 t; cvta.to.shared.u64 t, %1; cvt.u32.u64 %0, t; }" : "=r"(a) : "l"(p));
    return a;
}
__device__ __forceinline__ void cp_async16(uint32_t dst, const void* src, int szbytes){
    asm volatile("cp.async.cg.shared.global [%0], [%1], 16, %2;"
                 :: "r"(dst), "l"(src), "r"(szbytes) : "memory");
}
__device__ __forceinline__ void cp_async8(uint32_t dst, const void* src){
    asm volatile("cp.async.ca.shared.global [%0], [%1], 8;" :: "r"(dst), "l"(src) : "memory");
}
__device__ __forceinline__ void cp_async4(uint32_t dst, const void* src){
    asm volatile("cp.async.ca.shared.global [%0], [%1], 4;" :: "r"(dst), "l"(src) : "memory");
}
__device__ __forceinline__ void cp_commit(){ asm volatile("cp.async.commit_group;" ::: "memory"); }
__device__ __forceinline__ void cp_wait0(){ asm volatile("cp.async.wait_group 0;" ::: "memory"); }
#define CP_WAIT(N) asm volatile("cp.async.wait_group %0;" :: "n"(N) : "memory")

__device__ __forceinline__ void bsplit(float v, unsigned short& h, unsigned short& l){
    __nv_bfloat16 hb = __float2bfloat16(v);
    float r = v - __bfloat162float(hb);
    __nv_bfloat16 lb = __float2bfloat16(r);
    h = __bfloat16_as_ushort(hb); l = __bfloat16_as_ushort(lb);
}

__device__ __forceinline__ void mma16816(float* d, const uint32_t* a, uint32_t b0, uint32_t b1){
    asm volatile(
        "mma.sync.aligned.m16n8k16.row.col.f32.bf16.bf16.f32 "
        "{%0,%1,%2,%3}, {%4,%5,%6,%7}, {%8,%9}, {%0,%1,%2,%3};"
        : "+f"(d[0]), "+f"(d[1]), "+f"(d[2]), "+f"(d[3])
        : "r"(a[0]), "r"(a[1]), "r"(a[2]), "r"(a[3]), "r"(b0), "r"(b1));
}

// ---------------- weight prep ----------------
__global__ void wprep_kernel(const float* __restrict__ Wmsa)
{
    int slot = blockIdx.x;              // (kh*3+kw)*6 + cg
    int tap = slot / 6, cg = slot % 6;
    const int i0 = blockIdx.y * 1536;
    for (int idx = i0 + threadIdx.x; idx < i0 + 1536; idx += 256) {
        int o = idx >> 5, cil = idx & 31;
        int ci = cg*32 + cil;
        float w = Wmsa[(size_t)o*1728 + ci*9 + tap];
        unsigned short h, l; bsplit(w, h, l);
        g_Wh[(size_t)slot*6144 + idx] = h;
        g_Wl[(size_t)slot*6144 + idx] = l;
    }
}

// ---------------- x prep: NCHW float -> [n][y][x][c] split planes ----------------
__global__ void xprep_kernel(const float* __restrict__ x)
{
    __shared__ float row[64*130];
    const int y = blockIdx.x, n = blockIdx.y;
    const int tid = threadIdx.x;
    const float* src = x + (size_t)n*CHW + y*WW;
    for (int idx = tid; idx < 64*128; idx += 256) {
        int c = idx >> 7, xx = idx & 127;
        row[c*130 + xx] = src[(size_t)c*HW + xx];
    }
    __syncthreads();
    for (int idx = tid; idx < 128*16; idx += 256) {
        int xx = idx >> 4, c0 = (idx & 15)*4;
        ushort4 h4, l4;
        unsigned short h, l;
        bsplit(row[(c0+0)*130 + xx], h, l); h4.x = h; l4.x = l;
        bsplit(row[(c0+1)*130 + xx], h, l); h4.y = h; l4.y = l;
        bsplit(row[(c0+2)*130 + xx], h, l); h4.z = h; l4.z = l;
        bsplit(row[(c0+3)*130 + xx], h, l); h4.w = h; l4.w = l;
        size_t base = (((size_t)n*HH + y)*WW + xx)*64 + c0;
        *reinterpret_cast<ushort4*>(&g_xH[base]) = h4;
        *reinterpret_cast<ushort4*>(&g_xL[base]) = l4;
    }
}

// ---------------- attn kernel (256 threads, full-prefetch) ----------------
// smem floats: W0..W4 [64][65] @ k*4160, bias[5][64] @ 20800,
//   BufA @ 21120, BufP @ 29440, BufF @ 37760, BufR @ 46080 (each 64*130)
#define BSTRIDE 130
#define WSTRIDE 65
#define WREGF   4160        // floats per weight region
#define BIASF   20800
#define BUFAF   21120
#define BUFPF   29440
#define BUFFF   37760
#define BUFRF   46080
#define SMEM1_BYTES 217600

// prefetch one 64x128 row-block into stride-130 buffer (8B chunks)
__device__ __forceinline__ void cpa_row(uint32_t dst, const float* src, int tid){
    for (int idx = tid; idx < 4096; idx += 256) {
        int c = idx >> 6, m = idx & 63;
        cp_async8(dst + (uint32_t)(c*BSTRIDE + 2*m)*4, src + (size_t)c*HW + 2*m);
    }
}
// prefetch weight matrix (transposed into [k][o], stride 65) + bias
__device__ __forceinline__ void cpa_w(uint32_t dstW, const float* Wg,
                                      uint32_t dstB, const float* bg, int tid){
    for (int idx = tid; idx < 4096; idx += 256) {
        int o = idx >> 6, k = idx & 63;
        cp_async4(dstW + (uint32_t)(k*WSTRIDE + o)*4, Wg + o*64 + k);
    }
    if (tid < 64) cp_async4(dstB + tid*4, bg + tid);
}

// out[o] = sum_k Af[k*65+o] * B[k][pix]; A float (dup at use)
__device__ __forceinline__ void mm64pf(const float* __restrict__ Af,
                                       const float* __restrict__ Bm,
                                       int o0, int tx, ull acc[4][4]){
    #pragma unroll
    for (int i = 0; i < 4; i++)
        #pragma unroll
        for (int j = 0; j < 4; j++) acc[i][j] = 0ull;
    #pragma unroll 4
    for (int k = 0; k < 64; k++) {
        float w0 = Af[k*WSTRIDE + o0    ];
        float w1 = Af[k*WSTRIDE + o0 + 1];
        float w2 = Af[k*WSTRIDE + o0 + 2];
        float w3 = Af[k*WSTRIDE + o0 + 3];
        ull a0 = pk2(w0, w0), a1 = pk2(w1, w1), a2 = pk2(w2, w2), a3 = pk2(w3, w3);
        const float* bp = Bm + k*BSTRIDE + 2*tx;
        #pragma unroll
        for (int jj = 0; jj < 4; jj++) {
            ull b = *reinterpret_cast<const ull*>(bp + 32*jj);
            fma2(acc[0][jj], a0, b);
            fma2(acc[1][jj], a1, b);
            fma2(acc[2][jj], a2, b);
            fma2(acc[3][jj], a3, b);
        }
    }
}
// score[c][d] = sum_w Am[c][w]*Bm[d][w]; write SC[d*65+c] = s (float)
__device__ __forceinline__ void sc128p(const float* __restrict__ Am,
                                       const float* __restrict__ Bm,
                                       int o0, int tx, float* SC){
    ull acc[4][4];
    #pragma unroll
    for (int i = 0; i < 4; i++)
        #pragma unroll
        for (int j = 0; j < 4; j++) acc[i][j] = 0ull;
    #pragma unroll 4
    for (int kp = 0; kp < 64; kp++) {
        ull a[4], b[4];
        #pragma unroll
        for (int i = 0; i < 4; i++)
            a[i] = *reinterpret_cast<const ull*>(Am + (o0+i)*BSTRIDE + 2*kp);
        #pragma unroll
        for (int j = 0; j < 4; j++)
            b[j] = *reinterpret_cast<const ull*>(Bm + (tx+16*j)*BSTRIDE + 2*kp);
        #pragma unroll
        for (int i = 0; i < 4; i++)
            #pragma unroll
            for (int j = 0; j < 4; j++) fma2(acc[i][j], a[i], b[j]);
    }
    #pragma unroll
    for (int i = 0; i < 4; i++)
        #pragma unroll
        for (int j = 0; j < 4; j++) {
            float lo, hi; unpk(acc[i][j], lo, hi);
            SC[(tx+16*j)*WSTRIDE + o0 + i] = lo + hi;
        }
}
__device__ __forceinline__ void add_bias_store(float* Buf, ull acc[4][4],
                                               const float* bst, int o0, int tx){
    #pragma unroll
    for (int i = 0; i < 4; i++) {
        ull bb = pk2(bst[o0+i], bst[o0+i]);
        #pragma unroll
        for (int jj = 0; jj < 4; jj++)
            *reinterpret_cast<ull*>(Buf + (o0+i)*BSTRIDE + 2*tx + 32*jj) = add2(acc[i][jj], bb);
    }
}
__device__ __forceinline__ void store_feat_planes(
    unsigned short* __restrict__ gH, unsigned short* __restrict__ gL,
    ull acc[4][4], int n, int y, int o0, int tx)
{
    #pragma unroll
    for (int jj = 0; jj < 4; jj++) {
        float lo[4], hi[4];
        #pragma unroll
        for (int i = 0; i < 4; i++) unpk(acc[i][jj], lo[i], hi[i]);
        #pragma unroll
        for (int e = 0; e < 2; e++) {
            int xx = 2*tx + 32*jj + e;
            ushort4 h4, l4;
            unsigned short h, l;
            bsplit(e ? hi[0] : lo[0], h, l); h4.x = h; l4.x = l;
            bsplit(e ? hi[1] : lo[1], h, l); h4.y = h; l4.y = l;
            bsplit(e ? hi[2] : lo[2], h, l); h4.z = h; l4.z = l;
            bsplit(e ? hi[3] : lo[3], h, l); h4.w = h; l4.w = l;
            size_t base = (((size_t)n*HH + y)*WW + xx)*64 + o0;
            *reinterpret_cast<ushort4*>(&gH[base]) = h4;
            *reinterpret_cast<ushort4*>(&gL[base]) = l4;
        }
    }
}

__global__ void __launch_bounds__(256, 1)
attn_kernel(const float* __restrict__ x,  const float* __restrict__ xf, const float* __restrict__ xr,
            const float* __restrict__ Wx,  const float* __restrict__ bx,
            const float* __restrict__ Wx1, const float* __restrict__ bx1,
            const float* __restrict__ Wx2, const float* __restrict__ bx2,
            const float* __restrict__ Wxf, const float* __restrict__ bxf,
            const float* __restrict__ Wxr, const float* __restrict__ bxr)
{
    extern __shared__ float smf[];
    const uint32_t sb = smem_u32(smf);
    float* W0 = smf;                  // also score region after step 1
    float* W1 = smf + 1*WREGF;
    float* W2 = smf + 2*WREGF;
    float* W3 = smf + 3*WREGF;
    float* W4 = smf + 4*WREGF;
    float* bias = smf + BIASF;
    float* BufA = smf + BUFAF;
    float* BufP = smf + BUFPF;
    float* BufF = smf + BUFFF;
    float* BufR = smf + BUFRF;

    const int tid = threadIdx.x;
    const int ty = tid >> 4, tx = tid & 15;
    const int o0 = ty*4;
    const int y = blockIdx.x, n = blockIdx.y;
    const int rowoff = n*CHW + y*WW;

    // ---- prefetch everything in 5 commit groups ----
    cpa_row(sb + BUFAF*4, x + rowoff, tid);
    cpa_w(sb, Wx, sb + BIASF*4, bx, tid);
    cp_commit();                                             // g0
    cpa_row(sb + BUFFF*4, xf + rowoff, tid);
    cpa_w(sb + WREGF*4, Wxf, sb + (BIASF+64)*4, bxf, tid);
    cp_commit();                                             // g1
    cpa_w(sb + 2*WREGF*4, Wx1, sb + (BIASF+128)*4, bx1, tid);
    cp_commit();                                             // g2
    cpa_row(sb + BUFRF*4, xr + rowoff, tid);
    cpa_w(sb + 3*WREGF*4, Wxr, sb + (BIASF+192)*4, bxr, tid);
    cp_commit();                                             // g3
    cpa_w(sb + 4*WREGF*4, Wx2, sb + (BIASF+256)*4, bx2, tid);
    cp_commit();                                             // g4

    ull acc[4][4];

    // 1) xp = Wx@x + bx -> BufP
    CP_WAIT(4); __syncthreads();
    mm64pf(W0, BufA, o0, tx, acc);
    add_bias_store(BufP, acc, bias, o0, tx);
    __syncthreads();

    // 2) xfp = Wxf@xf + bxf -> BufF (in place)
    CP_WAIT(3); __syncthreads();
    mm64pf(W1, BufF, o0, tx, acc);
    __syncthreads();
    add_bias_store(BufF, acc, bias + 64, o0, tx);
    __syncthreads();

    // 3) x1 = Wx1@xp + bx1 -> BufA
    CP_WAIT(2); __syncthreads();
    mm64pf(W2, BufP, o0, tx, acc);
    add_bias_store(BufA, acc, bias + 128, o0, tx);
    __syncthreads();

    // 4) score1 = x1 . xfp^T -> SC (= W0 region, Wx is dead)
    sc128p(BufA, BufF, o0, tx, W0);
    __syncthreads();

    // 5) featF = score1 @ xp -> planes
    mm64pf(W0, BufP, o0, tx, acc);
    store_feat_planes(g_featFH, g_featFL, acc, n, y, o0, tx);

    // 6) xrp = Wxr@xr + bxr : read BufR, write BufF (dead)
    CP_WAIT(1); __syncthreads();
    mm64pf(W3, BufR, o0, tx, acc);
    add_bias_store(BufF, acc, bias + 192, o0, tx);

    // 7) x2 = Wx2@xp + bx2 -> BufA
    CP_WAIT(0); __syncthreads();
    mm64pf(W4, BufP, o0, tx, acc);
    add_bias_store(BufA, acc, bias + 256, o0, tx);
    __syncthreads();

    // 8) score2 = x2 . xrp^T -> SC
    sc128p(BufA, BufF, o0, tx, W0);
    __syncthreads();

    // 9) featR = score2 @ xp -> planes
    mm64pf(W0, BufP, o0, tx, acc);
    store_feat_planes(g_featRH, g_featRL, acc, n, y, o0, tx);
}

// ---------------- conv kernel: mma.sync bf16 (R11 proven version) ----------------
#define ATILE   15360   // 192*80
#define ABUF    92160
#define BPLANE  10400   // 130*80
#define BUFB    112960  // ABUF + 2*BPLANE
#define CONV_SMEM (2*BUFB)   // 225920

__device__ __forceinline__ void conv_issueA(uint32_t dst_base, int s, int tid)
{
    const int kh = s/6, cg = s - (s/6)*6;
    #pragma unroll 3
    for (int q = tid; q < 4608; q += 512) {
        int t   = q / 768;             // kw*2 + hl
        int rem = q - t*768;
        int o   = rem >> 2, c16 = rem & 3;
        int kw  = t >> 1,   hl = t & 1;
        int slot = (kh*3 + kw)*6 + cg;
        const unsigned short* src = (hl ? g_Wl : g_Wh) + (size_t)slot*6144 + o*32 + c16*8;
        cp_async16(dst_base + t*ATILE + o*80 + c16*16, src, 16);
    }
}

__device__ __forceinline__ void conv_issueB(uint32_t dst_base, int s, int n, int y, int tid)
{
    const int kh = s/6, cg = s - (s/6)*6;
    const unsigned short *pH, *pL;
    if      (cg < 2) { pH = g_featFH; pL = g_featFL; }
    else if (cg < 4) { pH = g_featRH; pL = g_featRL; }
    else             { pH = g_xH;     pL = g_xL;     }
    const int coff = (cg & 1)*32;
    const int iy = y - 1 + kh;
    const bool vrow = (iy >= 0 && iy < HH);
    #pragma unroll 3
    for (int q = tid; q < 1040; q += 512) {
        int col = q >> 3, t = q & 7;
        int plane = t >> 2, c16 = t & 3;
        int gx = col - 1;
        bool ok = vrow && gx >= 0 && gx < WW;
        const unsigned short* p = plane ? pL : pH;
        const unsigned short* src = ok
            ? p + (((size_t)n*HH + iy)*WW + gx)*64 + coff + c16*8
            : p;
        cp_async16(dst_base + ABUF + plane*BPLANE + col*80 + c16*16, src, ok ? 16 : 0);
    }
}

__global__ void __launch_bounds__(512, 1)
conv_mma_kernel(const float* __restrict__ bmsa, const float* __restrict__ gamma,
                const float* __restrict__ beta, const float* __restrict__ mean,
                const float* __restrict__ var,  float* __restrict__ out)
{
    extern __shared__ char smem[];
    const uint32_t smem_base = smem_u32(smem);
    const int tid  = threadIdx.x;
    const int lane = tid & 31, wid = tid >> 5;
    const int wm = wid >> 2;           // 0..3 -> M offset 48*wm
    const int wn = wid & 3;            // 0..3 -> N offset 32*wn
    const int y = blockIdx.x, n = blockIdx.y;

    float acc[3][4][4];
    #pragma unroll
    for (int mi = 0; mi < 3; mi++)
        #pragma unroll
        for (int nb = 0; nb < 4; nb++)
            #pragma unroll
            for (int e = 0; e < 4; e++) acc[mi][nb][e] = 0.f;

    // prologue: stage 0 into buf0
    conv_issueA(smem_base, 0, tid);
    conv_issueB(smem_base, 0, n, y, tid);
    cp_commit();

    const int acol = (lane & 3) * 4;
    const int arow = wm*48 + (lane >> 2);
    const int brow0 = wn*32 + (lane >> 2);

    for (int s = 0; s < 18; s++) {
        const int b = s & 1;
        const char* buf = smem + b*BUFB;

        cp_wait0();
        __syncthreads();

        if (s < 17) {
            conv_issueA(smem_base + (b^1)*BUFB, s+1, tid);
            conv_issueB(smem_base + (b^1)*BUFB, s+1, n, y, tid);
            cp_commit();
        }

        const char* Bh = buf + ABUF;
        const char* Bl = buf + ABUF + BPLANE;

        #pragma unroll
        for (int kw = 0; kw < 3; kw++) {
            const char* Ah = buf + (kw*2 + 0)*ATILE;
            const char* Al = buf + (kw*2 + 1)*ATILE;
            #pragma unroll
            for (int ks = 0; ks < 2; ks++) {
                const int koff = ks*32 + acol;
                uint32_t aF[3][4];
                uint32_t bH[4][2], bL[4][2];
                #pragma unroll
                for (int nb = 0; nb < 4; nb++) {
                    const char* q = Bh + (brow0 + nb*8 + kw)*80 + koff;
                    bH[nb][0] = *reinterpret_cast<const uint32_t*>(q);
                    bH[nb][1] = *reinterpret_cast<const uint32_t*>(q + 16);
                    const char* r = Bl + (brow0 + nb*8 + kw)*80 + koff;
                    bL[nb][0] = *reinterpret_cast<const uint32_t*>(r);
                    bL[nb][1] = *reinterpret_cast<const uint32_t*>(r + 16);
                }
                #pragma unroll
                for (int mi = 0; mi < 3; mi++) {
                    const char* p = Ah + (arow + mi*16)*80 + koff;
                    aF[mi][0] = *reinterpret_cast<const uint32_t*>(p);
                    aF[mi][1] = *reinterpret_cast<const uint32_t*>(p + 8*80);
                    aF[mi][2] = *reinterpret_cast<const uint32_t*>(p + 16);
                    aF[mi][3] = *reinterpret_cast<const uint32_t*>(p + 8*80 + 16);
                }
                #pragma unroll
                for (int nb = 0; nb < 4; nb++)
                    #pragma unroll
                    for (int mi = 0; mi < 3; mi++) {
                        mma16816(acc[mi][nb], aF[mi], bH[nb][0], bH[nb][1]);
                        mma16816(acc[mi][nb], aF[mi], bL[nb][0], bL[nb][1]);
                    }
                #pragma unroll
                for (int mi = 0; mi < 3; mi++) {
                    const char* p = Al + (arow + mi*16)*80 + koff;
                    aF[mi][0] = *reinterpret_cast<const uint32_t*>(p);
                    aF[mi][1] = *reinterpret_cast<const uint32_t*>(p + 8*80);
                    aF[mi][2] = *reinterpret_cast<const uint32_t*>(p + 16);
                    aF[mi][3] = *reinterpret_cast<const uint32_t*>(p + 8*80 + 16);
                }
                #pragma unroll
                for (int nb = 0; nb < 4; nb++)
                    #pragma unroll
                    for (int mi = 0; mi < 3; mi++)
                        mma16816(acc[mi][nb], aF[mi], bH[nb][0], bH[nb][1]);
            }
        }
    }

    // ---- epilogue: bias + BN + ReLU, float2 stores ----
    #pragma unroll
    for (int mi = 0; mi < 3; mi++) {
        #pragma unroll
        for (int h = 0; h < 2; h++) {
            const int o = wm*48 + mi*16 + (lane >> 2) + h*8;
            const float sc = gamma[o] * rsqrtf(var[o] + 1e-4f);
            const float t0 = (bmsa[o] - mean[o]) * sc + beta[o];
            float* orow = out + (((size_t)n*192 + o)*HH + y)*WW;
            #pragma unroll
            for (int nb = 0; nb < 4; nb++) {
                const int x0 = wn*32 + nb*8 + (lane & 3)*2;
                float v0 = fmaxf(fmaf(acc[mi][nb][h*2+0], sc, t0), 0.f);
                float v1 = fmaxf(fmaf(acc[mi][nb][h*2+1], sc, t0), 0.f);
                *reinterpret_cast<ull*>(orow + x0) = pk2(v0, v1);
            }
        }
    }
}

// ---------------- launch ----------------
extern "C" void kernel_launch(void* const* d_in, const int* in_sizes, int n_in,
                              void* d_out, int out_size)
{
    const float* x    = (const float*)d_in[0];
    const float* xf   = (const float*)d_in[1];
    const float* xr   = (const float*)d_in[2];
    const float* Wx   = (const float*)d_in[3];
    const float* bx   = (const float*)d_in[4];
    const float* Wx1  = (const float*)d_in[5];
    const float* bx1  = (const float*)d_in[6];
    const float* Wx2  = (const float*)d_in[7];
    const float* bx2  = (const float*)d_in[8];
    const float* Wxf  = (const float*)d_in[9];
    const float* bxf  = (const float*)d_in[10];
    const float* Wxr  = (const float*)d_in[11];
    const float* bxr  = (const float*)d_in[12];
    const float* Wmsa = (const float*)d_in[13];
    const float* bmsa = (const float*)d_in[14];
    const float* gam  = (const float*)d_in[15];
    const float* bet  = (const float*)d_in[16];
    const float* mu   = (const float*)d_in[17];
    const float* var  = (const float*)d_in[18];
    float* out = (float*)d_out;

    cudaFuncSetAttribute(attn_kernel, cudaFuncAttributeMaxDynamicSharedMemorySize, SMEM1_BYTES);
    cudaFuncSetAttribute(conv_mma_kernel, cudaFuncAttributeMaxDynamicSharedMemorySize, CONV_SMEM);

    dim3 gw(54, 4);
    wprep_kernel<<<gw, 256>>>(Wmsa);
    dim3 gx2(HH, BB);
    xprep_kernel<<<gx2, 256>>>(x);

    dim3 g1(HH, BB);
    attn_kernel<<<g1, 256, SMEM1_BYTES>>>(x, xf, xr, Wx, bx, Wx1, bx1, Wx2, bx2,
                                          Wxf, bxf, Wxr, bxr);

    dim3 g2(HH, BB);
    conv_mma_kernel<<<g2, 512, CONV_SMEM>>>(bmsa, gam, bet, mu, var, out);
}

// round 16
// speedup vs baseline: 1.3364x; 1.0134x over previous
#include <cuda_runtime.h>
#include <cuda_bf16.h>
#include <cstdint>

typedef unsigned long long ull;

#define CC   64
#define HH   128
#define WW   128
#define BB   8
#define HW   (HH*WW)        // 16384
#define CHW  (CC*HW)        // 1048576

// pre-split, pre-transposed planes: ushort [n][y][x][ci(64)]
__device__ unsigned short g_featFH[BB*HH*WW*64];
__device__ unsigned short g_featFL[BB*HH*WW*64];
__device__ unsigned short g_featRH[BB*HH*WW*64];
__device__ unsigned short g_featRL[BB*HH*WW*64];
__device__ unsigned short g_xH[BB*HH*WW*64];
__device__ unsigned short g_xL[BB*HH*WW*64];
// pre-split conv weights: [slot54][o192][ci32] ushort; slot = (kh*3+kw)*6+cg
__device__ unsigned short g_Wh[54*192*32];
__device__ unsigned short g_Wl[54*192*32];

// ---------------- f32x2 helpers ----------------
__device__ __forceinline__ ull pk2(float lo, float hi){
    ull r; asm("mov.b64 %0, {%1,%2};" : "=l"(r) : "f"(lo), "f"(hi)); return r;
}
__device__ __forceinline__ void unpk(ull a, float& lo, float& hi){
    asm("mov.b64 {%0,%1}, %2;" : "=f"(lo), "=f"(hi) : "l"(a));
}
__device__ __forceinline__ void fma2(ull& d, ull a, ull b){
    asm("fma.rn.f32x2 %0, %1, %2, %0;" : "+l"(d) : "l"(a), "l"(b));
}
__device__ __forceinline__ ull add2(ull a, ull b){
    ull r; asm("add.rn.f32x2 %0, %1, %2;" : "=l"(r) : "l"(a), "l"(b)); return r;
}

// ---------------- misc helpers ----------------
__device__ __forceinline__ uint32_t smem_u32(const void* p){
    uint32_t a;
    asm("{ .reg .u64 t; cvta.to.shared.u64 t, %1; cvt.u32.u64 %0, t; }" : "=r"(a) : "l"(p));
    return a;
}
__device__ __forceinline__ void cp_async16(uint32_t dst, const void* src, int szbytes){
    asm volatile("cp.async.cg.shared.global [%0], [%1], 16, %2;"
                 :: "r"(dst), "l"(src), "r"(szbytes) : "memory");
}
__device__ __forceinline__ void cp_async8(uint32_t dst, const void* src){
    asm volatile("cp.async.ca.shared.global [%0], [%1], 8;" :: "r"(dst), "l"(src) : "memory");
}
__device__ __forceinline__ void cp_async4(uint32_t dst, const void* src){
    asm volatile("cp.async.ca.shared.global [%0], [%1], 4;" :: "r"(dst), "l"(src) : "memory");
}
__device__ __forceinline__ void cp_commit(){ asm volatile("cp.async.commit_group;" ::: "memory"); }
__device__ __forceinline__ void cp_wait0(){ asm volatile("cp.async.wait_group 0;" ::: "memory"); }
#define CP_WAIT(N) asm volatile("cp.async.wait_group %0;" :: "n"(N) : "memory")

__device__ __forceinline__ void bsplit(float v, unsigned short& h, unsigned short& l){
    __nv_bfloat16 hb = __float2bfloat16(v);
    float r = v - __bfloat162float(hb);
    __nv_bfloat16 lb = __float2bfloat16(r);
    h = __bfloat16_as_ushort(hb); l = __bfloat16_as_ushort(lb);
}

__device__ __forceinline__ void mma16816(float* d, const uint32_t* a, uint32_t b0, uint32_t b1){
    asm volatile(
        "mma.sync.aligned.m16n8k16.row.col.f32.bf16.bf16.f32 "
        "{%0,%1,%2,%3}, {%4,%5,%6,%7}, {%8,%9}, {%0,%1,%2,%3};"
        : "+f"(d[0]), "+f"(d[1]), "+f"(d[2]), "+f"(d[3])
        : "r"(a[0]), "r"(a[1]), "r"(a[2]), "r"(a[3]), "r"(b0), "r"(b1));
}

// ---------------- weight prep ----------------
__global__ void wprep_kernel(const float* __restrict__ Wmsa)
{
    int slot = blockIdx.x;              // (kh*3+kw)*6 + cg
    int tap = slot / 6, cg = slot % 6;
    const int i0 = blockIdx.y * 1536;
    for (int idx = i0 + threadIdx.x; idx < i0 + 1536; idx += 256) {
        int o = idx >> 5, cil = idx & 31;
        int ci = cg*32 + cil;
        float w = Wmsa[(size_t)o*1728 + ci*9 + tap];
        unsigned short h, l; bsplit(w, h, l);
        g_Wh[(size_t)slot*6144 + idx] = h;
        g_Wl[(size_t)slot*6144 + idx] = l;
    }
}

// ---------------- x prep: NCHW float -> [n][y][x][c] split planes ----------------
__global__ void xprep_kernel(const float* __restrict__ x)
{
    __shared__ float row[64*130];
    const int y = blockIdx.x, n = blockIdx.y;
    const int tid = threadIdx.x;
    const float* src = x + (size_t)n*CHW + y*WW;
    for (int idx = tid; idx < 64*128; idx += 256) {
        int c = idx >> 7, xx = idx & 127;
        row[c*130 + xx] = src[(size_t)c*HW + xx];
    }
    __syncthreads();
    for (int idx = tid; idx < 128*16; idx += 256) {
        int xx = idx >> 4, c0 = (idx & 15)*4;
        ushort4 h4, l4;
        unsigned short h, l;
        bsplit(row[(c0+0)*130 + xx], h, l); h4.x = h; l4.x = l;
        bsplit(row[(c0+1)*130 + xx], h, l); h4.y = h; l4.y = l;
        bsplit(row[(c0+2)*130 + xx], h, l); h4.z = h; l4.z = l;
        bsplit(row[(c0+3)*130 + xx], h, l); h4.w = h; l4.w = l;
        size_t base = (((size_t)n*HH + y)*WW + xx)*64 + c0;
        *reinterpret_cast<ushort4*>(&g_xH[base]) = h4;
        *reinterpret_cast<ushort4*>(&g_xL[base]) = l4;
    }
}

// ---------------- attn kernel (256 threads, full-prefetch; R14 proven) ----------------
#define BSTRIDE 130
#define WSTRIDE 65
#define WREGF   4160        // floats per weight region
#define BIASF   20800
#define BUFAF   21120
#define BUFPF   29440
#define BUFFF   37760
#define BUFRF   46080
#define SMEM1_BYTES 217600

__device__ __forceinline__ void cpa_row(uint32_t dst, const float* src, int tid){
    for (int idx = tid; idx < 4096; idx += 256) {
        int c = idx >> 6, m = idx & 63;
        cp_async8(dst + (uint32_t)(c*BSTRIDE + 2*m)*4, src + (size_t)c*HW + 2*m);
    }
}
__device__ __forceinline__ void cpa_w(uint32_t dstW, const float* Wg,
                                      uint32_t dstB, const float* bg, int tid){
    for (int idx = tid; idx < 4096; idx += 256) {
        int o = idx >> 6, k = idx & 63;
        cp_async4(dstW + (uint32_t)(k*WSTRIDE + o)*4, Wg + o*64 + k);
    }
    if (tid < 64) cp_async4(dstB + tid*4, bg + tid);
}

__device__ __forceinline__ void mm64pf(const float* __restrict__ Af,
                                       const float* __restrict__ Bm,
                                       int o0, int tx, ull acc[4][4]){
    #pragma unroll
    for (int i = 0; i < 4; i++)
        #pragma unroll
        for (int j = 0; j < 4; j++) acc[i][j] = 0ull;
    #pragma unroll 4
    for (int k = 0; k < 64; k++) {
        float w0 = Af[k*WSTRIDE + o0    ];
        float w1 = Af[k*WSTRIDE + o0 + 1];
        float w2 = Af[k*WSTRIDE + o0 + 2];
        float w3 = Af[k*WSTRIDE + o0 + 3];
        ull a0 = pk2(w0, w0), a1 = pk2(w1, w1), a2 = pk2(w2, w2), a3 = pk2(w3, w3);
        const float* bp = Bm + k*BSTRIDE + 2*tx;
        #pragma unroll
        for (int jj = 0; jj < 4; jj++) {
            ull b = *reinterpret_cast<const ull*>(bp + 32*jj);
            fma2(acc[0][jj], a0, b);
            fma2(acc[1][jj], a1, b);
            fma2(acc[2][jj], a2, b);
            fma2(acc[3][jj], a3, b);
        }
    }
}
__device__ __forceinline__ void sc128p(const float* __restrict__ Am,
                                       const float* __restrict__ Bm,
                                       int o0, int tx, float* SC){
    ull acc[4][4];
    #pragma unroll
    for (int i = 0; i < 4; i++)
        #pragma unroll
        for (int j = 0; j < 4; j++) acc[i][j] = 0ull;
    #pragma unroll 4
    for (int kp = 0; kp < 64; kp++) {
        ull a[4], b[4];
        #pragma unroll
        for (int i = 0; i < 4; i++)
            a[i] = *reinterpret_cast<const ull*>(Am + (o0+i)*BSTRIDE + 2*kp);
        #pragma unroll
        for (int j = 0; j < 4; j++)
            b[j] = *reinterpret_cast<const ull*>(Bm + (tx+16*j)*BSTRIDE + 2*kp);
        #pragma unroll
        for (int i = 0; i < 4; i++)
            #pragma unroll
            for (int j = 0; j < 4; j++) fma2(acc[i][j], a[i], b[j]);
    }
    #pragma unroll
    for (int i = 0; i < 4; i++)
        #pragma unroll
        for (int j = 0; j < 4; j++) {
            float lo, hi; unpk(acc[i][j], lo, hi);
            SC[(tx+16*j)*WSTRIDE + o0 + i] = lo + hi;
        }
}
__device__ __forceinline__ void add_bias_store(float* Buf, ull acc[4][4],
                                               const float* bst, int o0, int tx){
    #pragma unroll
    for (int i = 0; i < 4; i++) {
        ull bb = pk2(bst[o0+i], bst[o0+i]);
        #pragma unroll
        for (int jj = 0; jj < 4; jj++)
            *reinterpret_cast<ull*>(Buf + (o0+i)*BSTRIDE + 2*tx + 32*jj) = add2(acc[i][jj], bb);
    }
}
__device__ __forceinline__ void store_feat_planes(
    unsigned short* __restrict__ gH, unsigned short* __restrict__ gL,
    ull acc[4][4], int n, int y, int o0, int tx)
{
    #pragma unroll
    for (int jj = 0; jj < 4; jj++) {
        float lo[4], hi[4];
        #pragma unroll
        for (int i = 0; i < 4; i++) unpk(acc[i][jj], lo[i], hi[i]);
        #pragma unroll
        for (int e = 0; e < 2; e++) {
            int xx = 2*tx + 32*jj + e;
            ushort4 h4, l4;
            unsigned short h, l;
            bsplit(e ? hi[0] : lo[0], h, l); h4.x = h; l4.x = l;
            bsplit(e ? hi[1] : lo[1], h, l); h4.y = h; l4.y = l;
            bsplit(e ? hi[2] : lo[2], h, l); h4.z = h; l4.z = l;
            bsplit(e ? hi[3] : lo[3], h, l); h4.w = h; l4.w = l;
            size_t base = (((size_t)n*HH + y)*WW + xx)*64 + o0;
            *reinterpret_cast<ushort4*>(&gH[base]) = h4;
            *reinterpret_cast<ushort4*>(&gL[base]) = l4;
        }
    }
}

__global__ void __launch_bounds__(256, 1)
attn_kernel(const float* __restrict__ x,  const float* __restrict__ xf, const float* __restrict__ xr,
            const float* __restrict__ Wx,  const float* __restrict__ bx,
            const float* __restrict__ Wx1, const float* __restrict__ bx1,
            const float* __restrict__ Wx2, const float* __restrict__ bx2,
            const float* __restrict__ Wxf, const float* __restrict__ bxf,
            const float* __restrict__ Wxr, const float* __restrict__ bxr)
{
    extern __shared__ float smf[];
    const uint32_t sb = smem_u32(smf);
    float* W0 = smf;                  // also score region after step 1
    float* W1 = smf + 1*WREGF;
    float* W2 = smf + 2*WREGF;
    float* W3 = smf + 3*WREGF;
    float* W4 = smf + 4*WREGF;
    float* bias = smf + BIASF;
    float* BufA = smf + BUFAF;
    float* BufP = smf + BUFPF;
    float* BufF = smf + BUFFF;
    float* BufR = smf + BUFRF;

    const int tid = threadIdx.x;
    const int ty = tid >> 4, tx = tid & 15;
    const int o0 = ty*4;
    const int y = blockIdx.x, n = blockIdx.y;
    const int rowoff = n*CHW + y*WW;

    cpa_row(sb + BUFAF*4, x + rowoff, tid);
    cpa_w(sb, Wx, sb + BIASF*4, bx, tid);
    cp_commit();                                             // g0
    cpa_row(sb + BUFFF*4, xf + rowoff, tid);
    cpa_w(sb + WREGF*4, Wxf, sb + (BIASF+64)*4, bxf, tid);
    cp_commit();                                             // g1
    cpa_w(sb + 2*WREGF*4, Wx1, sb + (BIASF+128)*4, bx1, tid);
    cp_commit();                                             // g2
    cpa_row(sb + BUFRF*4, xr + rowoff, tid);
    cpa_w(sb + 3*WREGF*4, Wxr, sb + (BIASF+192)*4, bxr, tid);
    cp_commit();                                             // g3
    cpa_w(sb + 4*WREGF*4, Wx2, sb + (BIASF+256)*4, bx2, tid);
    cp_commit();                                             // g4

    ull acc[4][4];

    CP_WAIT(4); __syncthreads();
    mm64pf(W0, BufA, o0, tx, acc);
    add_bias_store(BufP, acc, bias, o0, tx);
    __syncthreads();

    CP_WAIT(3); __syncthreads();
    mm64pf(W1, BufF, o0, tx, acc);
    __syncthreads();
    add_bias_store(BufF, acc, bias + 64, o0, tx);
    __syncthreads();

    CP_WAIT(2); __syncthreads();
    mm64pf(W2, BufP, o0, tx, acc);
    add_bias_store(BufA, acc, bias + 128, o0, tx);
    __syncthreads();

    sc128p(BufA, BufF, o0, tx, W0);
    __syncthreads();

    mm64pf(W0, BufP, o0, tx, acc);
    store_feat_planes(g_featFH, g_featFL, acc, n, y, o0, tx);

    CP_WAIT(1); __syncthreads();
    mm64pf(W3, BufR, o0, tx, acc);
    add_bias_store(BufF, acc, bias + 192, o0, tx);

    CP_WAIT(0); __syncthreads();
    mm64pf(W4, BufP, o0, tx, acc);
    add_bias_store(BufA, acc, bias + 256, o0, tx);
    __syncthreads();

    sc128p(BufA, BufF, o0, tx, W0);
    __syncthreads();

    mm64pf(W0, BufP, o0, tx, acc);
    store_feat_planes(g_featRH, g_featRL, acc, n, y, o0, tx);
}

// ---------------- conv kernel: mma.sync bf16, M split over 3 CTAs, occ 2 ----------------
// block=(y, n, ob): 64 out-ch x 128 px. 256 threads (8 warps: wm 0..1 -> M32, wn 0..3 -> N32).
// 18 stages (kh 0..2, cg 0..5). Per buffer:
//   A: 6 tiles [kw(3)][h/l(2)] of [64 o][32 k, 80B-stride]   = 30720 B
//   B: Bh,Bl [130 rows(x+1)][32 k, 80B-stride]               = 20800 B
#define ATILE   5120    // 64*80
#define ABUF    30720
#define BPLANE  10400   // 130*80
#define BUFB    51520   // ABUF + 2*BPLANE
#define CONV_SMEM (2*BUFB)   // 103040 -> 2 CTAs/SM

__device__ __forceinline__ void conv_issueA(uint32_t dst_base, int s, int ob, int tid)
{
    const int kh = s/6, cg = s - (s/6)*6;
    #pragma unroll 6
    for (int q = tid; q < 1536; q += 256) {
        int t   = q >> 8;              // kw*2 + hl
        int rem = q & 255;
        int o   = rem >> 2, c16 = rem & 3;
        int kw  = t >> 1,   hl = t & 1;
        int slot = (kh*3 + kw)*6 + cg;
        const unsigned short* src = (hl ? g_Wl : g_Wh) + (size_t)slot*6144 + (ob*64 + o)*32 + c16*8;
        cp_async16(dst_base + t*ATILE + o*80 + c16*16, src, 16);
    }
}

__device__ __forceinline__ void conv_issueB(uint32_t dst_base, int s, int n, int y, int tid)
{
    const int kh = s/6, cg = s - (s/6)*6;
    const unsigned short *pH, *pL;
    if      (cg < 2) { pH = g_featFH; pL = g_featFL; }
    else if (cg < 4) { pH = g_featRH; pL = g_featRL; }
    else             { pH = g_xH;     pL = g_xL;     }
    const int coff = (cg & 1)*32;
    const int iy = y - 1 + kh;
    const bool vrow = (iy >= 0 && iy < HH);
    #pragma unroll 5
    for (int q = tid; q < 1040; q += 256) {
        int col = q >> 3, t = q & 7;
        int plane = t >> 2, c16 = t & 3;
        int gx = col - 1;
        bool ok = vrow && gx >= 0 && gx < WW;
        const unsigned short* p = plane ? pL : pH;
        const unsigned short* src = ok
            ? p + (((size_t)n*HH + iy)*WW + gx)*64 + coff + c16*8
            : p;
        cp_async16(dst_base + ABUF + plane*BPLANE + col*80 + c16*16, src, ok ? 16 : 0);
    }
}

__global__ void __launch_bounds__(256, 2)
conv_mma_kernel(const float* __restrict__ bmsa, const float* __restrict__ gamma,
                const float* __restrict__ beta, const float* __restrict__ mean,
                const float* __restrict__ var,  float* __restrict__ out)
{
    extern __shared__ char smem[];
    const uint32_t smem_base = smem_u32(smem);
    const int tid  = threadIdx.x;
    const int lane = tid & 31, wid = tid >> 5;
    const int wm = wid >> 2;           // 0..1 -> M offset 32*wm
    const int wn = wid & 3;            // 0..3 -> N offset 32*wn
    const int y = blockIdx.x, n = blockIdx.y, ob = blockIdx.z;

    float acc[2][4][4];
    #pragma unroll
    for (int mi = 0; mi < 2; mi++)
        #pragma unroll
        for (int nb = 0; nb < 4; nb++)
            #pragma unroll
            for (int e = 0; e < 4; e++) acc[mi][nb][e] = 0.f;

    conv_issueA(smem_base, 0, ob, tid);
    conv_issueB(smem_base, 0, n, y, tid);
    cp_commit();

    const int acol = (lane & 3) * 4;
    const int arow = wm*32 + (lane >> 2);
    const int brow0 = wn*32 + (lane >> 2);

    for (int s = 0; s < 18; s++) {
        const int b = s & 1;
        const char* buf = smem + b*BUFB;

        cp_wait0();
        __syncthreads();

        if (s < 17) {
            conv_issueA(smem_base + (b^1)*BUFB, s+1, ob, tid);
            conv_issueB(smem_base + (b^1)*BUFB, s+1, n, y, tid);
            cp_commit();
        }

        const char* Bh = buf + ABUF;
        const char* Bl = buf + ABUF + BPLANE;

        #pragma unroll
        for (int kw = 0; kw < 3; kw++) {
            const char* Ah = buf + (kw*2 + 0)*ATILE;
            const char* Al = buf + (kw*2 + 1)*ATILE;
            #pragma unroll
            for (int ks = 0; ks < 2; ks++) {
                const int koff = ks*32 + acol;
                uint32_t aF[2][4];
                uint32_t bH[4][2], bL[4][2];
                #pragma unroll
                for (int nb = 0; nb < 4; nb++) {
                    const char* q = Bh + (brow0 + nb*8 + kw)*80 + koff;
                    bH[nb][0] = *reinterpret_cast<const uint32_t*>(q);
                    bH[nb][1] = *reinterpret_cast<const uint32_t*>(q + 16);
                    const char* r = Bl + (brow0 + nb*8 + kw)*80 + koff;
                    bL[nb][0] = *reinterpret_cast<const uint32_t*>(r);
                    bL[nb][1] = *reinterpret_cast<const uint32_t*>(r + 16);
                }
                #pragma unroll
                for (int mi = 0; mi < 2; mi++) {
                    const char* p = Ah + (arow + mi*16)*80 + koff;
                    aF[mi][0] = *reinterpret_cast<const uint32_t*>(p);
                    aF[mi][1] = *reinterpret_cast<const uint32_t*>(p + 8*80);
                    aF[mi][2] = *reinterpret_cast<const uint32_t*>(p + 16);
                    aF[mi][3] = *reinterpret_cast<const uint32_t*>(p + 8*80 + 16);
                }
                #pragma unroll
                for (int nb = 0; nb < 4; nb++)
                    #pragma unroll
                    for (int mi = 0; mi < 2; mi++) {
                        mma16816(acc[mi][nb], aF[mi], bH[nb][0], bH[nb][1]);
                        mma16816(acc[mi][nb], aF[mi], bL[nb][0], bL[nb][1]);
                    }
                #pragma unroll
                for (int mi = 0; mi < 2; mi++) {
                    const char* p = Al + (arow + mi*16)*80 + koff;
                    aF[mi][0] = *reinterpret_cast<const uint32_t*>(p);
                    aF[mi][1] = *reinterpret_cast<const uint32_t*>(p + 8*80);
                    aF[mi][2] = *reinterpret_cast<const uint32_t*>(p + 16);
                    aF[mi][3] = *reinterpret_cast<const uint32_t*>(p + 8*80 + 16);
                }
                #pragma unroll
                for (int nb = 0; nb < 4; nb++)
                    #pragma unroll
                    for (int mi = 0; mi < 2; mi++)
                        mma16816(acc[mi][nb], aF[mi], bH[nb][0], bH[nb][1]);
            }
        }
    }

    // ---- epilogue: bias + BN + ReLU, float2 stores ----
    #pragma unroll
    for (int mi = 0; mi < 2; mi++) {
        #pragma unroll
        for (int h = 0; h < 2; h++) {
            const int o = ob*64 + wm*32 + mi*16 + (lane >> 2) + h*8;
            const float sc = gamma[o] * rsqrtf(var[o] + 1e-4f);
            const float t0 = (bmsa[o] - mean[o]) * sc + beta[o];
            float* orow = out + (((size_t)n*192 + o)*HH + y)*WW;
            #pragma unroll
            for (int nb = 0; nb < 4; nb++) {
                const int x0 = wn*32 + nb*8 + (lane & 3)*2;
                float v0 = fmaxf(fmaf(acc[mi][nb][h*2+0], sc, t0), 0.f);
                float v1 = fmaxf(fmaf(acc[mi][nb][h*2+1], sc, t0), 0.f);
                *reinterpret_cast<ull*>(orow + x0) = pk2(v0, v1);
            }
        }
    }
}

// ---------------- launch ----------------
extern "C" void kernel_launch(void* const* d_in, const int* in_sizes, int n_in,
                              void* d_out, int out_size)
{
    const float* x    = (const float*)d_in[0];
    const float* xf   = (const float*)d_in[1];
    const float* xr   = (const float*)d_in[2];
    const float* Wx   = (const float*)d_in[3];
    const float* bx   = (const float*)d_in[4];
    const float* Wx1  = (const float*)d_in[5];
    const float* bx1  = (const float*)d_in[6];
    const float* Wx2  = (const float*)d_in[7];
    const float* bx2  = (const float*)d_in[8];
    const float* Wxf  = (const float*)d_in[9];
    const float* bxf  = (const float*)d_in[10];
    const float* Wxr  = (const float*)d_in[11];
    const float* bxr  = (const float*)d_in[12];
    const float* Wmsa = (const float*)d_in[13];
    const float* bmsa = (const float*)d_in[14];
    const float* gam  = (const float*)d_in[15];
    const float* bet  = (const float*)d_in[16];
    const float* mu   = (const float*)d_in[17];
    const float* var  = (const float*)d_in[18];
    float* out = (float*)d_out;

    cudaFuncSetAttribute(attn_kernel, cudaFuncAttributeMaxDynamicSharedMemorySize, SMEM1_BYTES);
    cudaFuncSetAttribute(conv_mma_kernel, cudaFuncAttributeMaxDynamicSharedMemorySize, CONV_SMEM);

    dim3 gw(54, 4);
    wprep_kernel<<<gw, 256>>>(Wmsa);
    dim3 gx2(HH, BB);
    xprep_kernel<<<gx2, 256>>>(x);

    dim3 g1(HH, BB);
    attn_kernel<<<g1, 256, SMEM1_BYTES>>>(x, xf, xr, Wx, bx, Wx1, bx1, Wx2, bx2,
                                          Wxf, bxf, Wxr, bxr);

    dim3 g2(HH, BB, 3);
    conv_mma_kernel<<<g2, 256, CONV_SMEM>>>(bmsa, gam, bet, mu, var, out);
}